// round 1
// baseline (speedup 1.0000x reference)
#include <cuda_runtime.h>
#include <cuda_bf16.h>
#include <math.h>

// Problem constants
#define B_  4
#define T_  2048
#define C_  1024
#define H_  16
#define HS_ 64
#define FF_ 4096
#define M_  (B_*T_)     // 8192 rows
#define EPS_ 1e-5f

// ---------------- scratch (no dynamic alloc allowed) ----------------
__device__ float g_h  [M_*C_];    // LN output (reused for LN1 and LN2)
__device__ float g_q  [M_*C_];
__device__ float g_k  [M_*C_];
__device__ float g_v  [M_*C_];
__device__ float g_o  [M_*C_];    // attention output (head-concat layout)
__device__ float g_x1 [M_*C_];    // x + attn_out @ Wproj + bproj
__device__ float g_ff [M_*FF_];   // relu(h2 @ W1 + b1)
__device__ float g_wqt[C_*C_];
__device__ float g_wkt[C_*C_];
__device__ float g_wvt[C_*C_];

// ---------------- LayerNorm: one block per row ----------------
__global__ __launch_bounds__(256) void ln_kernel(const float* __restrict__ x,
                                                 const float* __restrict__ g,
                                                 const float* __restrict__ b,
                                                 float* __restrict__ y)
{
    int row = blockIdx.x;
    const float* xr = x + (size_t)row * C_;
    float* yr = y + (size_t)row * C_;
    int tid = threadIdx.x;

    float s = 0.f, s2 = 0.f;
    #pragma unroll
    for (int i = tid; i < C_; i += 256) {
        float v = xr[i];
        s += v; s2 += v * v;
    }
    __shared__ float rs[256], rs2[256];
    rs[tid] = s; rs2[tid] = s2;
    __syncthreads();
    for (int off = 128; off > 0; off >>= 1) {
        if (tid < off) { rs[tid] += rs[tid+off]; rs2[tid] += rs2[tid+off]; }
        __syncthreads();
    }
    float mean = rs[0] * (1.0f / C_);
    float var  = rs2[0] * (1.0f / C_) - mean * mean;
    float rstd = rsqrtf(var + EPS_);
    #pragma unroll
    for (int i = tid; i < C_; i += 256) {
        yr[i] = (xr[i] - mean) * rstd * g[i] + b[i];
    }
}

// ---------------- repack [H,C,HS] -> [C, H*HS] ----------------
__global__ void repack_qkv(const float* __restrict__ W, float* __restrict__ Wt)
{
    int idx = blockIdx.x * 256 + threadIdx.x;   // idx = c*C + n,  n = h*HS + d
    if (idx < C_*C_) {
        int c = idx >> 10;
        int n = idx & (C_ - 1);
        int h = n >> 6;
        int d = n & (HS_ - 1);
        Wt[idx] = W[(size_t)h * C_ * HS_ + (size_t)c * HS_ + d];
    }
}

// ---------------- SGEMM: C = A[M,K] @ B[K,N] (+bias)(+res)(relu) ----------------
// 128x128 block tile, BK=16, 256 threads, 8x8 per thread.
__global__ __launch_bounds__(256) void gemm_kernel(const float* __restrict__ A,
                                                   const float* __restrict__ Bm,
                                                   float* __restrict__ Cm,
                                                   int Mn, int Nn, int Kn,
                                                   const float* __restrict__ bias,
                                                   const float* __restrict__ res,
                                                   int relu)
{
    __shared__ float As[128][16];
    __shared__ float Bs[16][128];

    int bm = blockIdx.x * 128;
    int bn = blockIdx.y * 128;
    int tid = threadIdx.x;
    int tx = tid & 15;       // 0..15  -> 8 cols each
    int ty = tid >> 4;       // 0..15  -> 8 rows each

    float acc[8][8];
    #pragma unroll
    for (int i = 0; i < 8; i++)
        #pragma unroll
        for (int j = 0; j < 8; j++) acc[i][j] = 0.f;

    for (int k0 = 0; k0 < Kn; k0 += 16) {
        __syncthreads();
        // A tile: 128x16 = 512 float4, 2 per thread
        #pragma unroll
        for (int i = 0; i < 2; i++) {
            int idx = tid + i * 256;
            int r = idx >> 2, c4 = idx & 3;
            float4 v = *(const float4*)(A + (size_t)(bm + r) * Kn + k0 + c4 * 4);
            *(float4*)&As[r][c4 * 4] = v;
        }
        // B tile: 16x128 = 512 float4, 2 per thread
        #pragma unroll
        for (int i = 0; i < 2; i++) {
            int idx = tid + i * 256;
            int r = idx >> 5, c4 = idx & 31;
            float4 v = *(const float4*)(Bm + (size_t)(k0 + r) * Nn + bn + c4 * 4);
            *(float4*)&Bs[r][c4 * 4] = v;
        }
        __syncthreads();

        #pragma unroll
        for (int kk = 0; kk < 16; kk++) {
            float ra[8], rb[8];
            #pragma unroll
            for (int i = 0; i < 8; i++) ra[i] = As[ty * 8 + i][kk];
            *(float4*)&rb[0] = *(const float4*)&Bs[kk][tx * 8];
            *(float4*)&rb[4] = *(const float4*)&Bs[kk][tx * 8 + 4];
            #pragma unroll
            for (int i = 0; i < 8; i++)
                #pragma unroll
                for (int j = 0; j < 8; j++)
                    acc[i][j] += ra[i] * rb[j];
        }
    }

    // epilogue
    #pragma unroll
    for (int i = 0; i < 8; i++) {
        int row = bm + ty * 8 + i;
        #pragma unroll
        for (int j = 0; j < 8; j++) {
            int col = bn + tx * 8 + j;
            float v = acc[i][j];
            if (bias) v += bias[col];
            if (res)  v += res[(size_t)row * Nn + col];
            if (relu) v = fmaxf(v, 0.f);
            Cm[(size_t)row * Nn + col] = v;
        }
    }
}

// ---------------- Flash attention: 32 queries x 64 keys per tile ----------------
// grid: (T/32, H, B), 256 threads: qi = tid>>3 (32 rows), sub = tid&7
__global__ __launch_bounds__(256) void attn_kernel(const float* __restrict__ q,
                                                   const float* __restrict__ k,
                                                   const float* __restrict__ v,
                                                   float* __restrict__ o)
{
    __shared__ float Qs[32][65];
    __shared__ float Ks[64][65];   // reused as P after scores
    __shared__ float Vs[64][65];

    const int qt0 = blockIdx.x * 32;
    const int h   = blockIdx.y;
    const int b   = blockIdx.z;
    const int tid = threadIdx.x;
    const int qi  = tid >> 3;
    const int sub = tid & 7;
    const float scale = 0.125f;   // HS^-0.5

    // load Q tile (32 x 64)
    const float* qbase = q + ((size_t)(b * T_ + qt0)) * C_ + h * HS_;
    #pragma unroll
    for (int i = 0; i < 2; i++) {
        int idx = tid + i * 256;   // 512 float4 total
        int r = idx >> 4, c4 = idx & 15;
        float4 val = *(const float4*)(qbase + (size_t)r * C_ + c4 * 4);
        Qs[r][c4 * 4 + 0] = val.x; Qs[r][c4 * 4 + 1] = val.y;
        Qs[r][c4 * 4 + 2] = val.z; Qs[r][c4 * 4 + 3] = val.w;
    }
    __syncthreads();

    float qreg[64];
    #pragma unroll
    for (int d = 0; d < 64; d++) qreg[d] = Qs[qi][d];

    float m = -INFINITY, l = 0.f;
    float acc[8];
    #pragma unroll
    for (int dd = 0; dd < 8; dd++) acc[dd] = 0.f;

    const int q_global = qt0 + qi;
    const int ntiles = (qt0 + 32 + 63) >> 6;

    for (int t = 0; t < ntiles; t++) {
        const int s0 = t * 64;
        __syncthreads();   // protect Ks(P)/Vs from previous iteration readers
        const float* kbase = k + ((size_t)(b * T_ + s0)) * C_ + h * HS_;
        const float* vbase = v + ((size_t)(b * T_ + s0)) * C_ + h * HS_;
        #pragma unroll
        for (int i = 0; i < 4; i++) {
            int idx = tid + i * 256;   // 1024 float4 total
            int r = idx >> 4, c4 = idx & 15;
            float4 kv = *(const float4*)(kbase + (size_t)r * C_ + c4 * 4);
            Ks[r][c4 * 4 + 0] = kv.x; Ks[r][c4 * 4 + 1] = kv.y;
            Ks[r][c4 * 4 + 2] = kv.z; Ks[r][c4 * 4 + 3] = kv.w;
            float4 vv = *(const float4*)(vbase + (size_t)r * C_ + c4 * 4);
            Vs[r][c4 * 4 + 0] = vv.x; Vs[r][c4 * 4 + 1] = vv.y;
            Vs[r][c4 * 4 + 2] = vv.z; Vs[r][c4 * 4 + 3] = vv.w;
        }
        __syncthreads();

        // scores: each thread handles j = sub + 8*jj
        float sv[8];
        #pragma unroll
        for (int jj = 0; jj < 8; jj++) sv[jj] = 0.f;
        #pragma unroll
        for (int d = 0; d < 64; d++) {
            float qd = qreg[d];
            #pragma unroll
            for (int jj = 0; jj < 8; jj++)
                sv[jj] += qd * Ks[sub + jj * 8][d];
        }
        float tmax = -INFINITY;
        #pragma unroll
        for (int jj = 0; jj < 8; jj++) {
            int j = sub + jj * 8;
            float s_ = sv[jj] * scale;
            if (s0 + j > q_global) s_ = -INFINITY;
            sv[jj] = s_;
            tmax = fmaxf(tmax, s_);
        }
        #pragma unroll
        for (int off = 4; off > 0; off >>= 1)
            tmax = fmaxf(tmax, __shfl_xor_sync(0xffffffffu, tmax, off));

        float mnew = fmaxf(m, tmax);
        float corr = __expf(m - mnew);
        float psum = 0.f;
        #pragma unroll
        for (int jj = 0; jj < 8; jj++) {
            float p = __expf(sv[jj] - mnew);
            sv[jj] = p;
            psum += p;
        }
        #pragma unroll
        for (int off = 4; off > 0; off >>= 1)
            psum += __shfl_xor_sync(0xffffffffu, psum, off);
        l = l * corr + psum;
        m = mnew;
        #pragma unroll
        for (int dd = 0; dd < 8; dd++) acc[dd] *= corr;

        __syncthreads();   // everyone done reading Ks as K
        // write P into Ks buffer: P[qi][j]
        #pragma unroll
        for (int jj = 0; jj < 8; jj++)
            Ks[qi][sub + jj * 8] = sv[jj];
        __syncwarp();      // P rows are produced & consumed within one warp

        // O += P @ V ; each thread owns dims d = sub + 8*dd
        #pragma unroll 8
        for (int j = 0; j < 64; j++) {
            float p = Ks[qi][j];
            #pragma unroll
            for (int dd = 0; dd < 8; dd++)
                acc[dd] += p * Vs[j][sub + dd * 8];
        }
    }

    float inv_l = 1.0f / l;
    float* obase = o + ((size_t)(b * T_ + q_global)) * C_ + h * HS_;
    #pragma unroll
    for (int dd = 0; dd < 8; dd++)
        obase[sub + dd * 8] = acc[dd] * inv_l;
}

// ---------------- launch ----------------
extern "C" void kernel_launch(void* const* d_in, const int* in_sizes, int n_in,
                              void* d_out, int out_size)
{
    const float* x     = (const float*)d_in[0];
    const float* Wq    = (const float*)d_in[1];
    const float* Wk    = (const float*)d_in[2];
    const float* Wv    = (const float*)d_in[3];
    const float* Wproj = (const float*)d_in[4];
    const float* bproj = (const float*)d_in[5];
    const float* W1    = (const float*)d_in[6];
    const float* b1    = (const float*)d_in[7];
    const float* W2    = (const float*)d_in[8];
    const float* b2    = (const float*)d_in[9];
    const float* ln1g  = (const float*)d_in[10];
    const float* ln1b  = (const float*)d_in[11];
    const float* ln2g  = (const float*)d_in[12];
    const float* ln2b  = (const float*)d_in[13];
    float* out = (float*)d_out;

    float *h, *qb, *kb, *vb, *ob, *x1, *ff, *wqt, *wkt, *wvt;
    cudaGetSymbolAddress((void**)&h,   g_h);
    cudaGetSymbolAddress((void**)&qb,  g_q);
    cudaGetSymbolAddress((void**)&kb,  g_k);
    cudaGetSymbolAddress((void**)&vb,  g_v);
    cudaGetSymbolAddress((void**)&ob,  g_o);
    cudaGetSymbolAddress((void**)&x1,  g_x1);
    cudaGetSymbolAddress((void**)&ff,  g_ff);
    cudaGetSymbolAddress((void**)&wqt, g_wqt);
    cudaGetSymbolAddress((void**)&wkt, g_wkt);
    cudaGetSymbolAddress((void**)&wvt, g_wvt);

    // 1. LN1
    ln_kernel<<<M_, 256>>>(x, ln1g, ln1b, h);

    // 2. repack per-head QKV weights to [C, C]
    repack_qkv<<<(C_*C_)/256, 256>>>(Wq, wqt);
    repack_qkv<<<(C_*C_)/256, 256>>>(Wk, wkt);
    repack_qkv<<<(C_*C_)/256, 256>>>(Wv, wvt);

    // 3. Q/K/V projections: [8192,1024] @ [1024,1024]
    dim3 g1(M_/128, C_/128);
    gemm_kernel<<<g1, 256>>>(h, wqt, qb, M_, C_, C_, nullptr, nullptr, 0);
    gemm_kernel<<<g1, 256>>>(h, wkt, kb, M_, C_, C_, nullptr, nullptr, 0);
    gemm_kernel<<<g1, 256>>>(h, wvt, vb, M_, C_, C_, nullptr, nullptr, 0);

    // 4. causal flash attention -> g_o ([B,T,H*HS] layout)
    dim3 ga(T_/32, H_, B_);
    attn_kernel<<<ga, 256>>>(qb, kb, vb, ob);

    // 5. x1 = x + o @ Wproj + bproj
    gemm_kernel<<<g1, 256>>>(ob, Wproj, x1, M_, C_, C_, bproj, x, 0);

    // 6. LN2
    ln_kernel<<<M_, 256>>>(x1, ln2g, ln2b, h);

    // 7. ff = relu(h @ W1 + b1) : [8192,1024]@[1024,4096]
    dim3 g2(M_/128, FF_/128);
    gemm_kernel<<<g2, 256>>>(h, W1, ff, M_, FF_, C_, b1, nullptr, 1);

    // 8. out = x1 + ff @ W2 + b2 : [8192,4096]@[4096,1024]
    dim3 g3(M_/128, C_/128);
    gemm_kernel<<<g3, 256>>>(ff, W2, out, M_, C_, FF_, b2, x1, 0);
}

// round 2
// speedup vs baseline: 2.0649x; 2.0649x over previous
#include <cuda_runtime.h>
#include <cuda_bf16.h>
#include <math.h>
#include <stdint.h>

// Problem constants
#define B_  4
#define T_  2048
#define C_  1024
#define C3_ 3072
#define H_  16
#define HS_ 64
#define FF_ 4096
#define M_  (B_*T_)     // 8192 rows
#define EPS_ 1e-5f

// ---------------- scratch (no dynamic alloc allowed) ----------------
__device__ float g_h   [M_*C_];    // LN output (reused for LN1 and LN2)
__device__ float g_qkv [M_*C3_];   // fused q|k|v, row stride 3072
__device__ float g_o   [M_*C_];    // attention output (head-concat layout)
__device__ float g_x1  [M_*C_];    // x + attn_out @ Wproj + bproj
__device__ float g_ff  [M_*FF_];   // relu(h2 @ W1 + b1)
__device__ float g_wqkv[C_*C3_];   // repacked [C, 3C] qkv weight

// ---------------- LayerNorm: one block per row ----------------
__global__ __launch_bounds__(256) void ln_kernel(const float* __restrict__ x,
                                                 const float* __restrict__ g,
                                                 const float* __restrict__ b,
                                                 float* __restrict__ y)
{
    int row = blockIdx.x;
    const float* xr = x + (size_t)row * C_;
    float* yr = y + (size_t)row * C_;
    int tid = threadIdx.x;

    float s = 0.f, s2 = 0.f;
    #pragma unroll
    for (int i = tid; i < C_; i += 256) {
        float v = xr[i];
        s += v; s2 += v * v;
    }
    __shared__ float rs[256], rs2[256];
    rs[tid] = s; rs2[tid] = s2;
    __syncthreads();
    for (int off = 128; off > 0; off >>= 1) {
        if (tid < off) { rs[tid] += rs[tid+off]; rs2[tid] += rs2[tid+off]; }
        __syncthreads();
    }
    float mean = rs[0] * (1.0f / C_);
    float var  = rs2[0] * (1.0f / C_) - mean * mean;
    float rstd = rsqrtf(var + EPS_);
    #pragma unroll
    for (int i = tid; i < C_; i += 256) {
        yr[i] = (xr[i] - mean) * rstd * g[i] + b[i];
    }
}

// ---------------- repack [H,C,HS]x3 -> [C, 3C] ----------------
__global__ void repack_qkv3(const float* __restrict__ Wq,
                            const float* __restrict__ Wk,
                            const float* __restrict__ Wv,
                            float* __restrict__ Wt)
{
    int idx = blockIdx.x * 256 + threadIdx.x;   // idx = c*3C + n
    if (idx < C_*C3_) {
        int c = idx / C3_;
        int n = idx - c * C3_;
        int sec = n >> 10;            // 0=q 1=k 2=v
        int nn = n & (C_ - 1);
        int h = nn >> 6;
        int d = nn & (HS_ - 1);
        const float* W = (sec == 0) ? Wq : (sec == 1) ? Wk : Wv;
        Wt[idx] = W[(size_t)h * C_ * HS_ + (size_t)c * HS_ + d];
    }
}

// ---------------- tf32 tensor-core GEMM ----------------
// C = A[M,K] @ B[K,N] (+bias)(+res)(relu)
// 128x128 block tile, BK=32, 256 threads (8 warps, each 64x32),
// mma.sync.m16n8k8.tf32, cp.async double-buffered smem.
#define BM 128
#define BN 128
#define BK 32
#define AS_STRIDE 36
#define BS_STRIDE 132
#define A_FLOATS (BM*AS_STRIDE)                       // 4608
#define STAGE_FLOATS (BM*AS_STRIDE + BK*BS_STRIDE)    // 8832
#define GEMM_SMEM_BYTES (2*STAGE_FLOATS*4)            // 70656

__device__ __forceinline__ uint32_t f2tf32(float f) {
    uint32_t u;
    asm("cvt.rna.tf32.f32 %0, %1;" : "=r"(u) : "f"(f));
    return u;
}

__device__ __forceinline__ void mma_tf32(float* c, const uint32_t* a, const uint32_t* b) {
    asm volatile("mma.sync.aligned.m16n8k8.row.col.f32.tf32.tf32.f32 "
        "{%0,%1,%2,%3}, {%4,%5,%6,%7}, {%8,%9}, {%0,%1,%2,%3};"
        : "+f"(c[0]), "+f"(c[1]), "+f"(c[2]), "+f"(c[3])
        : "r"(a[0]), "r"(a[1]), "r"(a[2]), "r"(a[3]), "r"(b[0]), "r"(b[1]));
}

__global__ __launch_bounds__(256, 2) void gemm_tf32(const float* __restrict__ A,
                                                    const float* __restrict__ Bm,
                                                    float* __restrict__ Cm,
                                                    int Mn, int Nn, int Kn,
                                                    const float* __restrict__ bias,
                                                    const float* __restrict__ res,
                                                    int relu)
{
    extern __shared__ float smbuf[];
    const int tid = threadIdx.x;
    const int wid = tid >> 5, lane = tid & 31;
    const int g = lane >> 2, tg = lane & 3;
    const int warp_m = wid >> 2;       // 0..1
    const int warp_n = wid & 3;        // 0..3
    const int bm = blockIdx.x * BM;
    const int bn = blockIdx.y * BN;

    float acc[4][4][4];
    #pragma unroll
    for (int mi = 0; mi < 4; mi++)
        #pragma unroll
        for (int ni = 0; ni < 4; ni++)
            #pragma unroll
            for (int r = 0; r < 4; r++) acc[mi][ni][r] = 0.f;

    auto load_tile = [&](int s, int k0) {
        float* As = smbuf + s * STAGE_FLOATS;
        float* Bs = As + A_FLOATS;
        #pragma unroll
        for (int i = 0; i < 4; i++) {
            int idx = tid + i * 256;                 // 1024 float4
            int r = idx >> 3, c = (idx & 7) * 4;
            uint32_t dst = (uint32_t)__cvta_generic_to_shared(As + r * AS_STRIDE + c);
            const float* src = A + (size_t)(bm + r) * Kn + k0 + c;
            asm volatile("cp.async.cg.shared.global [%0], [%1], 16;\n" :: "r"(dst), "l"(src));
        }
        #pragma unroll
        for (int i = 0; i < 4; i++) {
            int idx = tid + i * 256;                 // 1024 float4
            int r = idx >> 5, c = (idx & 31) * 4;
            uint32_t dst = (uint32_t)__cvta_generic_to_shared(Bs + r * BS_STRIDE + c);
            const float* src = Bm + (size_t)(k0 + r) * Nn + bn + c;
            asm volatile("cp.async.cg.shared.global [%0], [%1], 16;\n" :: "r"(dst), "l"(src));
        }
        asm volatile("cp.async.commit_group;\n");
    };

    const int ktiles = Kn / BK;
    load_tile(0, 0);

    for (int kt = 0; kt < ktiles; kt++) {
        const int cur = kt & 1;
        if (kt + 1 < ktiles) {
            load_tile(cur ^ 1, (kt + 1) * BK);
            asm volatile("cp.async.wait_group 1;\n");
        } else {
            asm volatile("cp.async.wait_group 0;\n");
        }
        __syncthreads();

        const float* As = smbuf + cur * STAGE_FLOATS;
        const float* Bs = As + A_FLOATS;

        #pragma unroll
        for (int ks = 0; ks < 4; ks++) {
            const int kb = ks * 8;
            uint32_t af[4][4], bf[4][2];
            #pragma unroll
            for (int mi = 0; mi < 4; mi++) {
                const float* ap = As + (warp_m * 64 + mi * 16 + g) * AS_STRIDE + kb + tg;
                af[mi][0] = f2tf32(ap[0]);
                af[mi][1] = f2tf32(ap[8 * AS_STRIDE]);
                af[mi][2] = f2tf32(ap[4]);
                af[mi][3] = f2tf32(ap[8 * AS_STRIDE + 4]);
            }
            #pragma unroll
            for (int ni = 0; ni < 4; ni++) {
                const float* bp = Bs + (kb + tg) * BS_STRIDE + warp_n * 32 + ni * 8 + g;
                bf[ni][0] = f2tf32(bp[0]);
                bf[ni][1] = f2tf32(bp[4 * BS_STRIDE]);
            }
            #pragma unroll
            for (int mi = 0; mi < 4; mi++)
                #pragma unroll
                for (int ni = 0; ni < 4; ni++)
                    mma_tf32(acc[mi][ni], af[mi], bf[ni]);
        }
        __syncthreads();
    }

    // epilogue: c0 (row g, col 2tg), c1 (row g, col 2tg+1), c2/c3 at row g+8
    #pragma unroll
    for (int mi = 0; mi < 4; mi++) {
        #pragma unroll
        for (int ni = 0; ni < 4; ni++) {
            int row0 = bm + warp_m * 64 + mi * 16 + g;
            int col  = bn + warp_n * 32 + ni * 8 + tg * 2;
            float bx = 0.f, by = 0.f;
            if (bias) { bx = bias[col]; by = bias[col + 1]; }
            #pragma unroll
            for (int half = 0; half < 2; half++) {
                int row = row0 + half * 8;
                float v0 = acc[mi][ni][half * 2 + 0] + bx;
                float v1 = acc[mi][ni][half * 2 + 1] + by;
                if (res) {
                    const float* rp = res + (size_t)row * Nn + col;
                    v0 += rp[0]; v1 += rp[1];
                }
                if (relu) { v0 = fmaxf(v0, 0.f); v1 = fmaxf(v1, 0.f); }
                float2 v = make_float2(v0, v1);
                *(float2*)(Cm + (size_t)row * Nn + col) = v;
            }
        }
    }
}

// ---------------- Flash attention: 32 queries x 64 keys per tile ----------------
// q/k/v point into fused qkv buffer with row stride ld (=3072).
__global__ __launch_bounds__(256) void attn_kernel(const float* __restrict__ q,
                                                   const float* __restrict__ k,
                                                   const float* __restrict__ v,
                                                   float* __restrict__ o,
                                                   int ld)
{
    __shared__ float Qs[32][65];
    __shared__ float Ks[64][65];   // reused as P after scores
    __shared__ float Vs[64][65];

    const int qt0 = blockIdx.x * 32;
    const int h   = blockIdx.y;
    const int b   = blockIdx.z;
    const int tid = threadIdx.x;
    const int qi  = tid >> 3;
    const int sub = tid & 7;
    const float scale = 0.125f;   // HS^-0.5

    // load Q tile (32 x 64)
    const float* qbase = q + ((size_t)(b * T_ + qt0)) * ld + h * HS_;
    #pragma unroll
    for (int i = 0; i < 2; i++) {
        int idx = tid + i * 256;   // 512 float4 total
        int r = idx >> 4, c4 = idx & 15;
        float4 val = *(const float4*)(qbase + (size_t)r * ld + c4 * 4);
        Qs[r][c4 * 4 + 0] = val.x; Qs[r][c4 * 4 + 1] = val.y;
        Qs[r][c4 * 4 + 2] = val.z; Qs[r][c4 * 4 + 3] = val.w;
    }
    __syncthreads();

    float qreg[64];
    #pragma unroll
    for (int d = 0; d < 64; d++) qreg[d] = Qs[qi][d];

    float m = -INFINITY, l = 0.f;
    float acc[8];
    #pragma unroll
    for (int dd = 0; dd < 8; dd++) acc[dd] = 0.f;

    const int q_global = qt0 + qi;
    const int ntiles = (qt0 + 32 + 63) >> 6;

    for (int t = 0; t < ntiles; t++) {
        const int s0 = t * 64;
        __syncthreads();
        const float* kbase = k + ((size_t)(b * T_ + s0)) * ld + h * HS_;
        const float* vbase = v + ((size_t)(b * T_ + s0)) * ld + h * HS_;
        #pragma unroll
        for (int i = 0; i < 4; i++) {
            int idx = tid + i * 256;   // 1024 float4 total
            int r = idx >> 4, c4 = idx & 15;
            float4 kv = *(const float4*)(kbase + (size_t)r * ld + c4 * 4);
            Ks[r][c4 * 4 + 0] = kv.x; Ks[r][c4 * 4 + 1] = kv.y;
            Ks[r][c4 * 4 + 2] = kv.z; Ks[r][c4 * 4 + 3] = kv.w;
            float4 vv = *(const float4*)(vbase + (size_t)r * ld + c4 * 4);
            Vs[r][c4 * 4 + 0] = vv.x; Vs[r][c4 * 4 + 1] = vv.y;
            Vs[r][c4 * 4 + 2] = vv.z; Vs[r][c4 * 4 + 3] = vv.w;
        }
        __syncthreads();

        float sv[8];
        #pragma unroll
        for (int jj = 0; jj < 8; jj++) sv[jj] = 0.f;
        #pragma unroll
        for (int d = 0; d < 64; d++) {
            float qd = qreg[d];
            #pragma unroll
            for (int jj = 0; jj < 8; jj++)
                sv[jj] += qd * Ks[sub + jj * 8][d];
        }
        float tmax = -INFINITY;
        #pragma unroll
        for (int jj = 0; jj < 8; jj++) {
            int j = sub + jj * 8;
            float s_ = sv[jj] * scale;
            if (s0 + j > q_global) s_ = -INFINITY;
            sv[jj] = s_;
            tmax = fmaxf(tmax, s_);
        }
        #pragma unroll
        for (int off = 4; off > 0; off >>= 1)
            tmax = fmaxf(tmax, __shfl_xor_sync(0xffffffffu, tmax, off));

        float mnew = fmaxf(m, tmax);
        float corr = __expf(m - mnew);
        float psum = 0.f;
        #pragma unroll
        for (int jj = 0; jj < 8; jj++) {
            float p = __expf(sv[jj] - mnew);
            sv[jj] = p;
            psum += p;
        }
        #pragma unroll
        for (int off = 4; off > 0; off >>= 1)
            psum += __shfl_xor_sync(0xffffffffu, psum, off);
        l = l * corr + psum;
        m = mnew;
        #pragma unroll
        for (int dd = 0; dd < 8; dd++) acc[dd] *= corr;

        __syncthreads();
        #pragma unroll
        for (int jj = 0; jj < 8; jj++)
            Ks[qi][sub + jj * 8] = sv[jj];
        __syncwarp();

        #pragma unroll 8
        for (int j = 0; j < 64; j++) {
            float p = Ks[qi][j];
            #pragma unroll
            for (int dd = 0; dd < 8; dd++)
                acc[dd] += p * Vs[j][sub + dd * 8];
        }
    }

    float inv_l = 1.0f / l;
    float* obase = o + ((size_t)(b * T_ + q_global)) * C_ + h * HS_;
    #pragma unroll
    for (int dd = 0; dd < 8; dd++)
        obase[sub + dd * 8] = acc[dd] * inv_l;
}

// ---------------- launch ----------------
extern "C" void kernel_launch(void* const* d_in, const int* in_sizes, int n_in,
                              void* d_out, int out_size)
{
    const float* x     = (const float*)d_in[0];
    const float* Wq    = (const float*)d_in[1];
    const float* Wk    = (const float*)d_in[2];
    const float* Wv    = (const float*)d_in[3];
    const float* Wproj = (const float*)d_in[4];
    const float* bproj = (const float*)d_in[5];
    const float* W1    = (const float*)d_in[6];
    const float* b1    = (const float*)d_in[7];
    const float* W2    = (const float*)d_in[8];
    const float* b2    = (const float*)d_in[9];
    const float* ln1g  = (const float*)d_in[10];
    const float* ln1b  = (const float*)d_in[11];
    const float* ln2g  = (const float*)d_in[12];
    const float* ln2b  = (const float*)d_in[13];
    float* out = (float*)d_out;

    float *h, *qkv, *ob, *x1, *ff, *wqkv;
    cudaGetSymbolAddress((void**)&h,    g_h);
    cudaGetSymbolAddress((void**)&qkv,  g_qkv);
    cudaGetSymbolAddress((void**)&ob,   g_o);
    cudaGetSymbolAddress((void**)&x1,   g_x1);
    cudaGetSymbolAddress((void**)&ff,   g_ff);
    cudaGetSymbolAddress((void**)&wqkv, g_wqkv);

    cudaFuncSetAttribute(gemm_tf32, cudaFuncAttributeMaxDynamicSharedMemorySize,
                         GEMM_SMEM_BYTES);

    // 1. LN1
    ln_kernel<<<M_, 256>>>(x, ln1g, ln1b, h);

    // 2. repack per-head QKV weights to [C, 3C]
    repack_qkv3<<<(C_*C3_)/256, 256>>>(Wq, Wk, Wv, wqkv);

    // 3. fused QKV projection: [8192,1024] @ [1024,3072]
    dim3 gqkv(M_/BM, C3_/BN);
    gemm_tf32<<<gqkv, 256, GEMM_SMEM_BYTES>>>(h, wqkv, qkv, M_, C3_, C_,
                                              nullptr, nullptr, 0);

    // 4. causal flash attention -> g_o ([B,T,H*HS] layout)
    dim3 ga(T_/32, H_, B_);
    attn_kernel<<<ga, 256>>>(qkv, qkv + C_, qkv + 2*C_, ob, C3_);

    // 5. x1 = x + o @ Wproj + bproj
    dim3 g1(M_/BM, C_/BN);
    gemm_tf32<<<g1, 256, GEMM_SMEM_BYTES>>>(ob, Wproj, x1, M_, C_, C_,
                                            bproj, x, 0);

    // 6. LN2
    ln_kernel<<<M_, 256>>>(x1, ln2g, ln2b, h);

    // 7. ff = relu(h @ W1 + b1) : [8192,1024]@[1024,4096]
    dim3 g2(M_/BM, FF_/BN);
    gemm_tf32<<<g2, 256, GEMM_SMEM_BYTES>>>(h, W1, ff, M_, FF_, C_,
                                            b1, nullptr, 1);

    // 8. out = x1 + ff @ W2 + b2 : [8192,4096]@[4096,1024]
    gemm_tf32<<<g1, 256, GEMM_SMEM_BYTES>>>(ff, W2, out, M_, C_, FF_,
                                            b2, x1, 0);
}

// round 3
// speedup vs baseline: 4.2102x; 2.0389x over previous
#include <cuda_runtime.h>
#include <cuda_bf16.h>
#include <math.h>
#include <stdint.h>

// Problem constants
#define B_  4
#define T_  2048
#define C_  1024
#define C3_ 3072
#define H_  16
#define HS_ 64
#define FF_ 4096
#define M_  (B_*T_)     // 8192 rows
#define EPS_ 1e-5f

// ---------------- scratch (no dynamic alloc allowed) ----------------
__device__ float g_h   [M_*C_];    // LN output (tf32-rounded)
__device__ float g_qkv [M_*C3_];   // fused q|k|v, row stride 3072 (tf32-rounded)
__device__ float g_o   [M_*C_];    // attention output (tf32-rounded)
__device__ float g_x1  [M_*C_];    // x + attn_out @ Wproj + bproj
__device__ float g_ff  [M_*FF_];   // relu(h2 @ W1 + b1) (tf32-rounded)
__device__ float g_wqkv[C_*C3_];   // repacked [C, 3C] qkv weight (tf32-rounded)
__device__ float g_wp  [C_*C_];    // tf32-rounded Wproj
__device__ float g_w1  [C_*FF_];   // tf32-rounded W1
__device__ float g_w2  [FF_*C_];   // tf32-rounded W2

__device__ __forceinline__ uint32_t f2tf32(float f) {
    uint32_t u;
    asm("cvt.rna.tf32.f32 %0, %1;" : "=r"(u) : "f"(f));
    return u;
}
__device__ __forceinline__ float roundtf(float f) {
    return __uint_as_float(f2tf32(f));
}

__device__ __forceinline__ void mma_tf32(float* c, const uint32_t* a, const uint32_t* b) {
    asm volatile("mma.sync.aligned.m16n8k8.row.col.f32.tf32.tf32.f32 "
        "{%0,%1,%2,%3}, {%4,%5,%6,%7}, {%8,%9}, {%0,%1,%2,%3};"
        : "+f"(c[0]), "+f"(c[1]), "+f"(c[2]), "+f"(c[3])
        : "r"(a[0]), "r"(a[1]), "r"(a[2]), "r"(a[3]), "r"(b[0]), "r"(b[1]));
}

// ---------------- LayerNorm: one block per row, tf32-rounded output ----------------
__global__ __launch_bounds__(256) void ln_kernel(const float* __restrict__ x,
                                                 const float* __restrict__ g,
                                                 const float* __restrict__ b,
                                                 float* __restrict__ y)
{
    int row = blockIdx.x;
    const float* xr = x + (size_t)row * C_;
    float* yr = y + (size_t)row * C_;
    int tid = threadIdx.x;

    float s = 0.f, s2 = 0.f;
    #pragma unroll
    for (int i = tid; i < C_; i += 256) {
        float v = xr[i];
        s += v; s2 += v * v;
    }
    __shared__ float rs[256], rs2[256];
    rs[tid] = s; rs2[tid] = s2;
    __syncthreads();
    for (int off = 128; off > 0; off >>= 1) {
        if (tid < off) { rs[tid] += rs[tid+off]; rs2[tid] += rs2[tid+off]; }
        __syncthreads();
    }
    float mean = rs[0] * (1.0f / C_);
    float var  = rs2[0] * (1.0f / C_) - mean * mean;
    float rstd = rsqrtf(var + EPS_);
    #pragma unroll
    for (int i = tid; i < C_; i += 256) {
        yr[i] = roundtf((xr[i] - mean) * rstd * g[i] + b[i]);
    }
}

// ---------------- repack [H,C,HS]x3 -> [C, 3C] tf32-rounded ----------------
__global__ void repack_qkv3(const float* __restrict__ Wq,
                            const float* __restrict__ Wk,
                            const float* __restrict__ Wv,
                            float* __restrict__ Wt)
{
    int idx = blockIdx.x * 256 + threadIdx.x;   // idx = c*3C + n
    if (idx < C_*C3_) {
        int c = idx / C3_;
        int n = idx - c * C3_;
        int sec = n >> 10;            // 0=q 1=k 2=v
        int nn = n & (C_ - 1);
        int h = nn >> 6;
        int d = nn & (HS_ - 1);
        const float* W = (sec == 0) ? Wq : (sec == 1) ? Wk : Wv;
        Wt[idx] = roundtf(W[(size_t)h * C_ * HS_ + (size_t)c * HS_ + d]);
    }
}

// ---------------- tf32 round-copy ----------------
__global__ void round_copy(const float* __restrict__ s, float* __restrict__ d, int n)
{
    int i = blockIdx.x * 256 + threadIdx.x;
    if (i < n) d[i] = roundtf(s[i]);
}

// ---------------- tf32 tensor-core GEMM ----------------
// C = A[M,K] @ B[K,N] (+bias)(+res)(relu)(round_out)
// A,B must be pre-rounded to tf32. 128x128 block, BK=32, 8 warps 64x32.
#define BM 128
#define BN 128
#define BK 32
#define AS_STRIDE 36
#define BS_STRIDE 132
#define A_FLOATS (BM*AS_STRIDE)                       // 4608
#define STAGE_FLOATS (BM*AS_STRIDE + BK*BS_STRIDE)    // 8832
#define GEMM_SMEM_BYTES (2*STAGE_FLOATS*4)            // 70656

__global__ __launch_bounds__(256, 2) void gemm_tf32(const float* __restrict__ A,
                                                    const float* __restrict__ Bm,
                                                    float* __restrict__ Cm,
                                                    int Mn, int Nn, int Kn,
                                                    const float* __restrict__ bias,
                                                    const float* __restrict__ res,
                                                    int relu, int round_out)
{
    extern __shared__ float smbuf[];
    const int tid = threadIdx.x;
    const int wid = tid >> 5, lane = tid & 31;
    const int g = lane >> 2, tg = lane & 3;
    const int warp_m = wid >> 2;       // 0..1
    const int warp_n = wid & 3;        // 0..3
    const int bm = blockIdx.x * BM;
    const int bn = blockIdx.y * BN;

    float acc[4][4][4];
    #pragma unroll
    for (int mi = 0; mi < 4; mi++)
        #pragma unroll
        for (int ni = 0; ni < 4; ni++)
            #pragma unroll
            for (int r = 0; r < 4; r++) acc[mi][ni][r] = 0.f;

    auto load_tile = [&](int s, int k0) {
        float* As = smbuf + s * STAGE_FLOATS;
        float* Bs = As + A_FLOATS;
        #pragma unroll
        for (int i = 0; i < 4; i++) {
            int idx = tid + i * 256;                 // 1024 float4
            int r = idx >> 3, c = (idx & 7) * 4;
            uint32_t dst = (uint32_t)__cvta_generic_to_shared(As + r * AS_STRIDE + c);
            const float* src = A + (size_t)(bm + r) * Kn + k0 + c;
            asm volatile("cp.async.cg.shared.global [%0], [%1], 16;\n" :: "r"(dst), "l"(src));
        }
        #pragma unroll
        for (int i = 0; i < 4; i++) {
            int idx = tid + i * 256;                 // 1024 float4
            int r = idx >> 5, c = (idx & 31) * 4;
            uint32_t dst = (uint32_t)__cvta_generic_to_shared(Bs + r * BS_STRIDE + c);
            const float* src = Bm + (size_t)(k0 + r) * Nn + bn + c;
            asm volatile("cp.async.cg.shared.global [%0], [%1], 16;\n" :: "r"(dst), "l"(src));
        }
        asm volatile("cp.async.commit_group;\n");
    };

    const int ktiles = Kn / BK;
    load_tile(0, 0);

    for (int kt = 0; kt < ktiles; kt++) {
        const int cur = kt & 1;
        if (kt + 1 < ktiles) {
            load_tile(cur ^ 1, (kt + 1) * BK);
            asm volatile("cp.async.wait_group 1;\n");
        } else {
            asm volatile("cp.async.wait_group 0;\n");
        }
        __syncthreads();

        const float* As = smbuf + cur * STAGE_FLOATS;
        const float* Bs = As + A_FLOATS;

        #pragma unroll
        for (int ks = 0; ks < 4; ks++) {
            const int kb = ks * 8;
            uint32_t af[4][4], bf[4][2];
            #pragma unroll
            for (int mi = 0; mi < 4; mi++) {
                const float* ap = As + (warp_m * 64 + mi * 16 + g) * AS_STRIDE + kb + tg;
                af[mi][0] = __float_as_uint(ap[0]);
                af[mi][1] = __float_as_uint(ap[8 * AS_STRIDE]);
                af[mi][2] = __float_as_uint(ap[4]);
                af[mi][3] = __float_as_uint(ap[8 * AS_STRIDE + 4]);
            }
            #pragma unroll
            for (int ni = 0; ni < 4; ni++) {
                const float* bp = Bs + (kb + tg) * BS_STRIDE + warp_n * 32 + ni * 8 + g;
                bf[ni][0] = __float_as_uint(bp[0]);
                bf[ni][1] = __float_as_uint(bp[4 * BS_STRIDE]);
            }
            #pragma unroll
            for (int mi = 0; mi < 4; mi++)
                #pragma unroll
                for (int ni = 0; ni < 4; ni++)
                    mma_tf32(acc[mi][ni], af[mi], bf[ni]);
        }
        __syncthreads();
    }

    #pragma unroll
    for (int mi = 0; mi < 4; mi++) {
        #pragma unroll
        for (int ni = 0; ni < 4; ni++) {
            int row0 = bm + warp_m * 64 + mi * 16 + g;
            int col  = bn + warp_n * 32 + ni * 8 + tg * 2;
            float bx = 0.f, by = 0.f;
            if (bias) { bx = bias[col]; by = bias[col + 1]; }
            #pragma unroll
            for (int half = 0; half < 2; half++) {
                int row = row0 + half * 8;
                float v0 = acc[mi][ni][half * 2 + 0] + bx;
                float v1 = acc[mi][ni][half * 2 + 1] + by;
                if (res) {
                    const float* rp = res + (size_t)row * Nn + col;
                    v0 += rp[0]; v1 += rp[1];
                }
                if (relu) { v0 = fmaxf(v0, 0.f); v1 = fmaxf(v1, 0.f); }
                if (round_out) { v0 = roundtf(v0); v1 = roundtf(v1); }
                float2 v = make_float2(v0, v1);
                *(float2*)(Cm + (size_t)row * Nn + col) = v;
            }
        }
    }
}

// ---------------- tensor-core flash attention ----------------
// 128 queries/block, 8 warps (m16 each), 64-key tiles, mma tf32.
// qkv pre-rounded to tf32.  Output tf32-rounded.
#define KSTR 68
#define VSTR 72
#define PSTR 68
#define ATTN_SMEM ((2*64*KSTR + 2*64*VSTR + 128*PSTR)*4)   // 106496

__global__ __launch_bounds__(256) void attn_tc(const float* __restrict__ qkv,
                                               float* __restrict__ o)
{
    extern __shared__ float sm[];
    float* Ks = sm;                      // 2 stages of 64 x KSTR
    float* Vs = sm + 2*64*KSTR;          // 2 stages of 64 x VSTR
    float* Ps = Vs + 2*64*VSTR;          // 128 x PSTR (Q staging, then P)

    const int tid = threadIdx.x, wid = tid >> 5, lane = tid & 31;
    const int g = lane >> 2, tg = lane & 3;
    const int qt0 = blockIdx.x * 128;
    const int h = blockIdx.y, b = blockIdx.z;

    const float* qbase = qkv + (size_t)(b * T_ + qt0) * C3_ + h * HS_;
    const float* kbase = qkv + (size_t)b * T_ * C3_ + C_  + h * HS_;
    const float* vbase = qkv + (size_t)b * T_ * C3_ + 2*C_ + h * HS_;

    // stage Q tile (128x64) into Ps
    #pragma unroll
    for (int i = 0; i < 8; i++) {
        int idx = tid + i * 256;
        int r = idx >> 4, c = (idx & 15) * 4;
        float4 v = *(const float4*)(qbase + (size_t)r * C3_ + c);
        *(float4*)&Ps[r * PSTR + c] = v;
    }
    __syncthreads();

    const int m0 = wid * 16;
    uint32_t qf[8][4];          // Q pre-scaled by 1/8 (exact in tf32)
    #pragma unroll
    for (int k = 0; k < 8; k++) {
        const float* p = Ps + (m0 + g) * PSTR + k * 8 + tg;
        qf[k][0] = __float_as_uint(p[0] * 0.125f);
        qf[k][1] = __float_as_uint(p[8 * PSTR] * 0.125f);
        qf[k][2] = __float_as_uint(p[4] * 0.125f);
        qf[k][3] = __float_as_uint(p[8 * PSTR + 4] * 0.125f);
    }

    float mrow0 = -INFINITY, mrow1 = -INFINITY, lrow0 = 0.f, lrow1 = 0.f;
    float oacc[8][4];
    #pragma unroll
    for (int j = 0; j < 8; j++)
        #pragma unroll
        for (int r = 0; r < 4; r++) oacc[j][r] = 0.f;

    const int r0 = qt0 + m0 + g;       // this thread's first query row
    const int my_max = qt0 + m0 + 15;  // warp's last query row
    const int ntiles = (qt0 + 128) >> 6;

    auto loadKV = [&](int s, int s0) {
        const float* kp = kbase + (size_t)s0 * C3_;
        const float* vp = vbase + (size_t)s0 * C3_;
        float* Kd = Ks + s * 64 * KSTR;
        float* Vd = Vs + s * 64 * VSTR;
        #pragma unroll
        for (int i = 0; i < 4; i++) {
            int idx = tid + i * 256;
            int r = idx >> 4, c = (idx & 15) * 4;
            uint32_t dk = (uint32_t)__cvta_generic_to_shared(Kd + r * KSTR + c);
            asm volatile("cp.async.cg.shared.global [%0], [%1], 16;\n"
                         :: "r"(dk), "l"(kp + (size_t)r * C3_ + c));
            uint32_t dv = (uint32_t)__cvta_generic_to_shared(Vd + r * VSTR + c);
            asm volatile("cp.async.cg.shared.global [%0], [%1], 16;\n"
                         :: "r"(dv), "l"(vp + (size_t)r * C3_ + c));
        }
        asm volatile("cp.async.commit_group;\n");
    };

    loadKV(0, 0);

    for (int t = 0; t < ntiles; t++) {
        const int s0 = t * 64;
        if (t + 1 < ntiles) {
            loadKV((t + 1) & 1, s0 + 64);
            asm volatile("cp.async.wait_group 1;\n");
        } else {
            asm volatile("cp.async.wait_group 0;\n");
        }
        __syncthreads();

        if (s0 <= my_max) {
            const float* Kt = Ks + (t & 1) * 64 * KSTR;
            const float* Vt = Vs + (t & 1) * 64 * VSTR;

            // S = (Q/8) @ K^T
            float sf[8][4];
            #pragma unroll
            for (int j = 0; j < 8; j++)
                #pragma unroll
                for (int r = 0; r < 4; r++) sf[j][r] = 0.f;
            #pragma unroll
            for (int k = 0; k < 8; k++) {
                #pragma unroll
                for (int j = 0; j < 8; j++) {
                    uint32_t bf[2];
                    const float* kp = Kt + (j * 8 + g) * KSTR + k * 8 + tg;
                    bf[0] = __float_as_uint(kp[0]);
                    bf[1] = __float_as_uint(kp[4]);
                    mma_tf32(sf[j], qf[k], bf);
                }
            }

            // causal mask + online softmax (rows r0, r0+8)
            float mx0 = -INFINITY, mx1 = -INFINITY;
            #pragma unroll
            for (int j = 0; j < 8; j++) {
                int c0 = s0 + j * 8 + 2 * tg, c1 = c0 + 1;
                if (c0 > r0)     sf[j][0] = -INFINITY;
                if (c1 > r0)     sf[j][1] = -INFINITY;
                if (c0 > r0 + 8) sf[j][2] = -INFINITY;
                if (c1 > r0 + 8) sf[j][3] = -INFINITY;
                mx0 = fmaxf(mx0, fmaxf(sf[j][0], sf[j][1]));
                mx1 = fmaxf(mx1, fmaxf(sf[j][2], sf[j][3]));
            }
            mx0 = fmaxf(mx0, __shfl_xor_sync(0xffffffffu, mx0, 1));
            mx0 = fmaxf(mx0, __shfl_xor_sync(0xffffffffu, mx0, 2));
            mx1 = fmaxf(mx1, __shfl_xor_sync(0xffffffffu, mx1, 1));
            mx1 = fmaxf(mx1, __shfl_xor_sync(0xffffffffu, mx1, 2));

            float mn0 = fmaxf(mrow0, mx0), mn1 = fmaxf(mrow1, mx1);
            float corr0 = __expf(mrow0 - mn0), corr1 = __expf(mrow1 - mn1);
            float sum0 = 0.f, sum1 = 0.f;
            #pragma unroll
            for (int j = 0; j < 8; j++) {
                sf[j][0] = __expf(sf[j][0] - mn0);
                sf[j][1] = __expf(sf[j][1] - mn0);
                sf[j][2] = __expf(sf[j][2] - mn1);
                sf[j][3] = __expf(sf[j][3] - mn1);
                sum0 += sf[j][0] + sf[j][1];
                sum1 += sf[j][2] + sf[j][3];
            }
            sum0 += __shfl_xor_sync(0xffffffffu, sum0, 1);
            sum0 += __shfl_xor_sync(0xffffffffu, sum0, 2);
            sum1 += __shfl_xor_sync(0xffffffffu, sum1, 1);
            sum1 += __shfl_xor_sync(0xffffffffu, sum1, 2);
            lrow0 = lrow0 * corr0 + sum0;
            lrow1 = lrow1 * corr1 + sum1;
            mrow0 = mn0; mrow1 = mn1;
            #pragma unroll
            for (int j = 0; j < 8; j++) {
                oacc[j][0] *= corr0; oacc[j][1] *= corr0;
                oacc[j][2] *= corr1; oacc[j][3] *= corr1;
            }

            // store P (tf32-rounded) into this warp's rows of Ps
            __syncwarp();
            #pragma unroll
            for (int j = 0; j < 8; j++) {
                float* pp = Ps + (m0 + g) * PSTR + j * 8 + 2 * tg;
                pp[0] = __uint_as_float(f2tf32(sf[j][0]));
                pp[1] = __uint_as_float(f2tf32(sf[j][1]));
                pp[8 * PSTR]     = __uint_as_float(f2tf32(sf[j][2]));
                pp[8 * PSTR + 1] = __uint_as_float(f2tf32(sf[j][3]));
            }
            __syncwarp();

            // O += P @ V
            #pragma unroll
            for (int k = 0; k < 8; k++) {
                uint32_t af[4];
                const float* ap = Ps + (m0 + g) * PSTR + k * 8 + tg;
                af[0] = __float_as_uint(ap[0]);
                af[1] = __float_as_uint(ap[8 * PSTR]);
                af[2] = __float_as_uint(ap[4]);
                af[3] = __float_as_uint(ap[8 * PSTR + 4]);
                #pragma unroll
                for (int j = 0; j < 8; j++) {
                    uint32_t bf[2];
                    const float* vp = Vt + (k * 8 + tg) * VSTR + j * 8 + g;
                    bf[0] = __float_as_uint(vp[0]);
                    bf[1] = __float_as_uint(vp[4 * VSTR]);
                    mma_tf32(oacc[j], af, bf);
                }
            }
        }
        __syncthreads();
    }

    // epilogue: normalize, round, write (feeds proj GEMM)
    float inv0 = 1.f / lrow0;
    float inv1 = 1.f / lrow1;
    float* ob0 = o + ((size_t)(b * T_ + r0)) * C_ + h * HS_;
    float* ob1 = ob0 + (size_t)8 * C_;
    #pragma unroll
    for (int j = 0; j < 8; j++) {
        int col = j * 8 + 2 * tg;
        float2 v0 = make_float2(roundtf(oacc[j][0] * inv0), roundtf(oacc[j][1] * inv0));
        float2 v1 = make_float2(roundtf(oacc[j][2] * inv1), roundtf(oacc[j][3] * inv1));
        *(float2*)(ob0 + col) = v0;
        *(float2*)(ob1 + col) = v1;
    }
}

// ---------------- launch ----------------
extern "C" void kernel_launch(void* const* d_in, const int* in_sizes, int n_in,
                              void* d_out, int out_size)
{
    const float* x     = (const float*)d_in[0];
    const float* Wq    = (const float*)d_in[1];
    const float* Wk    = (const float*)d_in[2];
    const float* Wv    = (const float*)d_in[3];
    const float* Wproj = (const float*)d_in[4];
    const float* bproj = (const float*)d_in[5];
    const float* W1    = (const float*)d_in[6];
    const float* b1    = (const float*)d_in[7];
    const float* W2    = (const float*)d_in[8];
    const float* b2    = (const float*)d_in[9];
    const float* ln1g  = (const float*)d_in[10];
    const float* ln1b  = (const float*)d_in[11];
    const float* ln2g  = (const float*)d_in[12];
    const float* ln2b  = (const float*)d_in[13];
    float* out = (float*)d_out;

    float *h, *qkv, *ob, *x1, *ff, *wqkv, *wp, *w1, *w2;
    cudaGetSymbolAddress((void**)&h,    g_h);
    cudaGetSymbolAddress((void**)&qkv,  g_qkv);
    cudaGetSymbolAddress((void**)&ob,   g_o);
    cudaGetSymbolAddress((void**)&x1,   g_x1);
    cudaGetSymbolAddress((void**)&ff,   g_ff);
    cudaGetSymbolAddress((void**)&wqkv, g_wqkv);
    cudaGetSymbolAddress((void**)&wp,   g_wp);
    cudaGetSymbolAddress((void**)&w1,   g_w1);
    cudaGetSymbolAddress((void**)&w2,   g_w2);

    cudaFuncSetAttribute(gemm_tf32, cudaFuncAttributeMaxDynamicSharedMemorySize,
                         GEMM_SMEM_BYTES);
    cudaFuncSetAttribute(attn_tc, cudaFuncAttributeMaxDynamicSharedMemorySize,
                         ATTN_SMEM);

    // 1. LN1 (tf32-rounded out)
    ln_kernel<<<M_, 256>>>(x, ln1g, ln1b, h);

    // 2. weight prep (all tf32-rounded)
    repack_qkv3<<<(C_*C3_)/256, 256>>>(Wq, Wk, Wv, wqkv);
    round_copy<<<(C_*C_)/256, 256>>>(Wproj, wp, C_*C_);
    round_copy<<<(C_*FF_)/256, 256>>>(W1, w1, C_*FF_);
    round_copy<<<(FF_*C_)/256, 256>>>(W2, w2, FF_*C_);

    // 3. fused QKV projection: [8192,1024] @ [1024,3072], rounded out
    dim3 gqkv(M_/BM, C3_/BN);
    gemm_tf32<<<gqkv, 256, GEMM_SMEM_BYTES>>>(h, wqkv, qkv, M_, C3_, C_,
                                              nullptr, nullptr, 0, 1);

    // 4. tensor-core causal flash attention -> g_o
    dim3 ga(T_/128, H_, B_);
    attn_tc<<<ga, 256, ATTN_SMEM>>>(qkv, ob);

    // 5. x1 = x + o @ Wproj + bproj   (fp32 out)
    dim3 g1(M_/BM, C_/BN);
    gemm_tf32<<<g1, 256, GEMM_SMEM_BYTES>>>(ob, wp, x1, M_, C_, C_,
                                            bproj, x, 0, 0);

    // 6. LN2 (tf32-rounded out)
    ln_kernel<<<M_, 256>>>(x1, ln2g, ln2b, h);

    // 7. ff = relu(h @ W1 + b1), rounded out
    dim3 g2(M_/BM, FF_/BN);
    gemm_tf32<<<g2, 256, GEMM_SMEM_BYTES>>>(h, w1, ff, M_, FF_, C_,
                                            b1, nullptr, 1, 1);

    // 8. out = x1 + ff @ W2 + b2  (final, fp32 out)
    gemm_tf32<<<g1, 256, GEMM_SMEM_BYTES>>>(ff, w2, out, M_, C_, FF_,
                                            b2, x1, 0, 0);
}